// round 1
// baseline (speedup 1.0000x reference)
#include <cuda_runtime.h>

#define D 64
#define NCAP 100000
#define ECAP 1600000
#define GCAP 128
#define BN_EPS 1e-5f

// ---------------- device scratch (no allocations allowed) ----------------
__device__ int   g_degcnt[NCAP];
__device__ int   g_off[NCAP + 1];
__device__ int   g_cur[NCAP];
__device__ int   g_csr[ECAP];
__device__ float g_invdeg[NCAP];
__device__ float g_gcnt[GCAP];
__device__ float g_invg[GCAP];
__device__ float g_h[NCAP * D];
__device__ float g_pre[NCAP * D];
__device__ float g_z[NCAP * D];
__device__ float g_stats[2 * D];
__device__ float g_ab[2 * D];

// ---------------- init: zero counters + g_pool region ----------------
__global__ void k_init(int n, int g, float* __restrict__ gp) {
    int i = blockIdx.x * blockDim.x + threadIdx.x;
    if (i < n) g_degcnt[i] = 0;
    if (i < g) g_gcnt[i] = 0.0f;
    if (i < g * D) gp[i] = 0.0f;
}

// ---------------- in-degree histogram ----------------
__global__ void k_deg(const int* __restrict__ dst, int e) {
    int i = blockIdx.x * blockDim.x + threadIdx.x;
    if (i < e) atomicAdd(&g_degcnt[dst[i]], 1);
}

// ---------------- per-graph node counts ----------------
__global__ void k_gcnt(const int* __restrict__ batch, int n) {
    int i = blockIdx.x * blockDim.x + threadIdx.x;
    if (i < n) atomicAdd(&g_gcnt[batch[i]], 1.0f);
}

__global__ void k_invg(int g) {
    int i = threadIdx.x;
    if (i < g) g_invg[i] = 1.0f / fmaxf(g_gcnt[i], 1.0f);
}

// ---------------- single-block exclusive scan (4 elems/thread) -----------
__global__ void k_scan(int n) {
    __shared__ int warpsum[32];
    __shared__ int s_carry;
    int tid  = threadIdx.x;
    int lane = tid & 31;
    int wid  = tid >> 5;
    if (tid == 0) s_carry = 0;
    __syncthreads();
    const int CH = 4096;  // 1024 threads * 4
    for (int base = 0; base < n; base += CH) {
        int i0 = base + tid * 4;
        int v[4];
#pragma unroll
        for (int k = 0; k < 4; k++) {
            int i = i0 + k;
            v[k] = (i < n) ? g_degcnt[i] : 0;
        }
        int s  = v[0] + v[1] + v[2] + v[3];
        int sc = s;  // inclusive warp scan of s
#pragma unroll
        for (int o = 1; o < 32; o <<= 1) {
            int t = __shfl_up_sync(0xffffffffu, sc, o);
            if (lane >= o) sc += t;
        }
        if (lane == 31) warpsum[wid] = sc;
        __syncthreads();
        if (wid == 0) {
            int ws = warpsum[lane];
#pragma unroll
            for (int o = 1; o < 32; o <<= 1) {
                int t = __shfl_up_sync(0xffffffffu, ws, o);
                if (lane >= o) ws += t;
            }
            warpsum[lane] = ws;
        }
        __syncthreads();
        int carry = s_carry;
        int wbase = (wid > 0) ? warpsum[wid - 1] : 0;
        int run   = carry + wbase + (sc - s);  // exclusive base for this thread
#pragma unroll
        for (int k = 0; k < 4; k++) {
            int i = i0 + k;
            if (i < n) {
                g_off[i]    = run;
                g_cur[i]    = run;
                g_invdeg[i] = 1.0f / fmaxf((float)v[k], 1.0f);
                run += v[k];
            }
        }
        __syncthreads();
        if (tid == blockDim.x - 1) s_carry = carry + wbase + sc;
        __syncthreads();
    }
    if (threadIdx.x == 0) g_off[n] = s_carry;
}

// ---------------- CSR scatter ----------------
__global__ void k_scatter(const int* __restrict__ src, const int* __restrict__ dst, int e) {
    int i = blockIdx.x * blockDim.x + threadIdx.x;
    if (i < e) {
        int pos    = atomicAdd(&g_cur[dst[i]], 1);
        g_csr[pos] = src[i];
    }
}

// ---------------- aggregation: pre = h + mean_{src->i} h[src]  (warp/node)
__global__ __launch_bounds__(256) void k_agg(const float* __restrict__ x, int n, int first) {
    int node = (blockIdx.x * blockDim.x + threadIdx.x) >> 5;
    int lane = threadIdx.x & 31;
    if (node >= n) return;
    const float* __restrict__ hin = first ? x : (const float*)g_h;
    int beg = g_off[node], end = g_off[node + 1];
    float2 acc = make_float2(0.0f, 0.0f);
    for (int j = beg; j < end; j++) {
        int s    = g_csr[j];
        float2 v = *(const float2*)(hin + s * D + lane * 2);
        acc.x += v.x;
        acc.y += v.y;
    }
    float inv  = g_invdeg[node];
    float2 hv  = *(const float2*)(hin + node * D + lane * 2);
    float2 o;
    o.x = hv.x + acc.x * inv;
    o.y = hv.y + acc.y * inv;
    *(float2*)(g_pre + node * D + lane * 2) = o;
}

// ---------------- GEMM 64x64 tiles, 4x4 per thread --------------------
// MODE 0: z = pre @ W1 + b1          (X = g_pre, Y = g_z)
// MODE 1: h = relu(bn(z)) @ W2 + b2  (X = g_z with BN+ReLU, Y = g_h, pool)
template <int MODE>
__global__ __launch_bounds__(256) void k_gemm(const float* __restrict__ W,
                                              const float* __restrict__ bias,
                                              float* __restrict__ pool, int n, int addflag) {
    __shared__ float sW[64 * 64];
    __shared__ float sX[64 * 68];  // transposed, padded: sX[col*68 + row]
    int tid  = threadIdx.x;
    int brow = blockIdx.x * 64;
    const float* __restrict__ X = (MODE == 0) ? (const float*)g_pre : (const float*)g_z;
    float* __restrict__ Y       = (MODE == 0) ? g_z : g_h;

    // stage W (coalesced)
    {
        const float4* W4 = (const float4*)W;
        float4* sW4      = (float4*)sW;
#pragma unroll
        for (int e = tid; e < 1024; e += 256) sW4[e] = W4[e];
    }
    // stage X transposed. Mapping: row varies within warp -> conflict-free STS
    for (int e = tid; e < 1024; e += 256) {
        int r   = e & 63;   // tile row
        int c4  = e >> 6;   // float4 column group 0..15
        int row = brow + r;
        float4 v = make_float4(0.f, 0.f, 0.f, 0.f);
        if (row < n) v = *(const float4*)(X + row * D + c4 * 4);
        int c = c4 * 4;
        if (MODE == 1) {
            v.x = fmaxf(fmaf(v.x, g_ab[c + 0], g_ab[64 + c + 0]), 0.f);
            v.y = fmaxf(fmaf(v.y, g_ab[c + 1], g_ab[64 + c + 1]), 0.f);
            v.z = fmaxf(fmaf(v.z, g_ab[c + 2], g_ab[64 + c + 2]), 0.f);
            v.w = fmaxf(fmaf(v.w, g_ab[c + 3], g_ab[64 + c + 3]), 0.f);
        }
        sX[(c + 0) * 68 + r] = v.x;
        sX[(c + 1) * 68 + r] = v.y;
        sX[(c + 2) * 68 + r] = v.z;
        sX[(c + 3) * 68 + r] = v.w;
    }
    __syncthreads();

    int tx = tid & 15, ty = tid >> 4;
    float4 a0 = make_float4(0.f, 0.f, 0.f, 0.f), a1 = a0, a2 = a0, a3 = a0;
#pragma unroll
    for (int k = 0; k < 64; k++) {
        float4 w  = *(const float4*)&sW[k * 64 + tx * 4];
        float4 xv = *(const float4*)&sX[k * 68 + ty * 4];
        a0.x = fmaf(xv.x, w.x, a0.x); a0.y = fmaf(xv.x, w.y, a0.y);
        a0.z = fmaf(xv.x, w.z, a0.z); a0.w = fmaf(xv.x, w.w, a0.w);
        a1.x = fmaf(xv.y, w.x, a1.x); a1.y = fmaf(xv.y, w.y, a1.y);
        a1.z = fmaf(xv.y, w.z, a1.z); a1.w = fmaf(xv.y, w.w, a1.w);
        a2.x = fmaf(xv.z, w.x, a2.x); a2.y = fmaf(xv.z, w.y, a2.y);
        a2.z = fmaf(xv.z, w.z, a2.z); a2.w = fmaf(xv.z, w.w, a2.w);
        a3.x = fmaf(xv.w, w.x, a3.x); a3.y = fmaf(xv.w, w.y, a3.y);
        a3.z = fmaf(xv.w, w.z, a3.z); a3.w = fmaf(xv.w, w.w, a3.w);
    }

    float4 bv = *(const float4*)(bias + tx * 4);
    float4 accs[4] = {a0, a1, a2, a3};
#pragma unroll
    for (int i = 0; i < 4; i++) {
        int r = brow + ty * 4 + i;
        if (r < n) {
            float4 o = accs[i];
            o.x += bv.x; o.y += bv.y; o.z += bv.z; o.w += bv.w;
            *(float4*)(Y + r * D + tx * 4) = o;
            if (MODE == 1) {
                float4* pp = (float4*)(pool + r * D + tx * 4);
                if (addflag) {
                    float4 p = *pp;
                    p.x += o.x; p.y += o.y; p.z += o.z; p.w += o.w;
                    *pp = p;
                } else {
                    *pp = o;
                }
            }
        }
    }
}

// ---------------- BN statistics ----------------
__global__ void k_zstat() {
    if (threadIdx.x < 2 * D) g_stats[threadIdx.x] = 0.0f;
}

__global__ __launch_bounds__(256) void k_stats(int n) {
    int col = threadIdx.x & 63;
    int rg  = threadIdx.x >> 6;  // 0..3
    float s = 0.f, q = 0.f;
    for (int r = blockIdx.x * 4 + rg; r < n; r += gridDim.x * 4) {
        float v = g_z[r * D + col];
        s += v;
        q += v * v;
    }
    __shared__ float ss[4][64];
    __shared__ float qq[4][64];
    ss[rg][col] = s;
    qq[rg][col] = q;
    __syncthreads();
    if (threadIdx.x < 64) {
        int c   = threadIdx.x;
        float S = ss[0][c] + ss[1][c] + ss[2][c] + ss[3][c];
        float Q = qq[0][c] + qq[1][c] + qq[2][c] + qq[3][c];
        atomicAdd(&g_stats[c], S);
        atomicAdd(&g_stats[64 + c], Q);
    }
}

__global__ void k_bnparams(const float* __restrict__ gamma, const float* __restrict__ beta, int n) {
    int c = threadIdx.x;
    if (c < D) {
        float invN = 1.0f / (float)n;
        float mean = g_stats[c] * invN;
        float var  = g_stats[64 + c] * invN - mean * mean;
        float a    = gamma[c] * rsqrtf(var + BN_EPS);
        g_ab[c]      = a;
        g_ab[64 + c] = beta[c] - mean * a;
    }
}

// ---------------- graph pooling: gp = inv_gcnt * segsum(node_pool) -------
__global__ __launch_bounds__(256) void k_gpool(const float* __restrict__ np,
                                               const int* __restrict__ batch,
                                               float* __restrict__ gp, int n) {
    int idx = blockIdx.x * blockDim.x + threadIdx.x;
    if (idx < n * D) {
        int row = idx >> 6;
        int col = idx & 63;
        int b   = batch[row];
        atomicAdd(&gp[b * D + col], np[idx] * g_invg[b]);
    }
}

// ---------------- launch ----------------
extern "C" void kernel_launch(void* const* d_in, const int* in_sizes, int n_in,
                              void* d_out, int out_size) {
    const float* x     = (const float*)d_in[0];
    const int*   ei    = (const int*)d_in[1];
    const int*   batch = (const int*)d_in[2];
    const float* W1    = (const float*)d_in[3];
    const float* b1    = (const float*)d_in[4];
    const float* gamma = (const float*)d_in[5];
    const float* beta  = (const float*)d_in[6];
    const float* W2    = (const float*)d_in[7];
    const float* b2    = (const float*)d_in[8];

    int n = in_sizes[0] / D;
    int e = in_sizes[1] / 2;
    int L = in_sizes[3] / (D * D);
    if (n > NCAP || e > ECAP) return;

    float* np = (float*)d_out;               // node_pool [n, D]
    float* gp = np + (size_t)n * D;          // g_pool    [g, D]
    int g = (out_size - n * D) / D;
    if (g > GCAP) return;

    const int* src = ei;
    const int* dst = ei + e;

    int nb256  = (n + 255) / 256;
    int eb256  = (e + 255) / 256;

    // graph structure (per call; deterministic)
    k_init<<<nb256, 256>>>(n, g, gp);
    k_deg<<<eb256, 256>>>(dst, e);
    k_gcnt<<<nb256, 256>>>(batch, n);
    k_scan<<<1, 1024>>>(n);
    k_invg<<<1, 128>>>(g);
    k_scatter<<<eb256, 256>>>(src, dst, e);

    int aggBlocks  = (n * 32 + 255) / 256;
    int gemmBlocks = (n + 63) / 64;

    for (int l = 0; l < L; l++) {
        k_agg<<<aggBlocks, 256>>>(x, n, l == 0 ? 1 : 0);
        k_gemm<0><<<gemmBlocks, 256>>>(W1 + l * D * D, b1 + l * D, nullptr, n, 0);
        k_zstat<<<1, 128>>>();
        k_stats<<<512, 256>>>(n);
        k_bnparams<<<1, 64>>>(gamma + l * D, beta + l * D, n);
        k_gemm<1><<<gemmBlocks, 256>>>(W2 + l * D * D, b2 + l * D, np, n, l == 0 ? 0 : 1);
    }

    k_gpool<<<(n * D + 255) / 256, 256>>>(np, batch, gp, n);
}

// round 4
// speedup vs baseline: 1.1532x; 1.1532x over previous
#include <cuda_runtime.h>

#define D 64
#define NCAP 100000
#define ECAP 1600000
#define GCAP 128
#define BN_EPS 1e-5f

// ---------------- device scratch ----------------
__device__ int   g_degcnt[NCAP];
__device__ int   g_off[NCAP + 1];
__device__ int   g_cur[NCAP];
__device__ int   g_csr[ECAP];
__device__ float g_invdeg[NCAP];
__device__ float g_gcnt[GCAP];
__device__ float g_invg[GCAP];
__device__ float g_h[NCAP * D];
__device__ float g_pre[NCAP * D];
__device__ float g_z[NCAP * D];
__device__ float g_stats[2 * D];
__device__ float g_ab[2 * D];
__device__ int   g_bsum[128];
__device__ int   g_boff[128];

// ---------------- init: zero counters + g_pool region ----------------
__global__ void k_init(int n, int g, float* __restrict__ gp) {
    int i = blockIdx.x * blockDim.x + threadIdx.x;
    if (i < n) g_degcnt[i] = 0;
    if (i < g) g_gcnt[i] = 0.0f;
    if (i < g * D) gp[i] = 0.0f;
}

__global__ void k_deg(const int* __restrict__ dst, int e) {
    int i = blockIdx.x * blockDim.x + threadIdx.x;
    if (i < e) atomicAdd(&g_degcnt[dst[i]], 1);
}

__global__ void k_gcnt(const int* __restrict__ batch, int n) {
    int i = blockIdx.x * blockDim.x + threadIdx.x;
    if (i < n) atomicAdd(&g_gcnt[batch[i]], 1.0f);
}

// ---------------- two-level scan: pass 1, per-block reduce (1024/block) ---
__global__ __launch_bounds__(256) void k_scan1(int n) {
    int tid = threadIdx.x;
    int i0  = blockIdx.x * 1024 + tid * 4;
    int s = 0;
#pragma unroll
    for (int k = 0; k < 4; k++) {
        int i = i0 + k;
        if (i < n) s += g_degcnt[i];
    }
#pragma unroll
    for (int o = 16; o > 0; o >>= 1) s += __shfl_down_sync(0xffffffffu, s, o);
    __shared__ int ws[8];
    if ((tid & 31) == 0) ws[tid >> 5] = s;
    __syncthreads();
    if (tid == 0) {
        int t = 0;
#pragma unroll
        for (int k = 0; k < 8; k++) t += ws[k];
        g_bsum[blockIdx.x] = t;
    }
}

// ---------------- scan pass 2: scan block sums (1 block) + invg + off[n] --
__global__ void k_scan2(int nblk, int n, int e, int g) {
    int tid = threadIdx.x, lane = tid & 31, w = tid >> 5;
    int v  = (tid < nblk) ? g_bsum[tid] : 0;
    int sc = v;
#pragma unroll
    for (int o = 1; o < 32; o <<= 1) {
        int t = __shfl_up_sync(0xffffffffu, sc, o);
        if (lane >= o) sc += t;
    }
    __shared__ int ws[4];
    if (lane == 31) ws[w] = sc;
    __syncthreads();
    int off = 0;
    for (int k = 0; k < w; k++) off += ws[k];
    if (tid < nblk) g_boff[tid] = off + sc - v;
    if (tid == 0) g_off[n] = e;
    if (tid < g) g_invg[tid] = 1.0f / fmaxf(g_gcnt[tid], 1.0f);
}

// ---------------- scan pass 3: local scan + global offset ----------------
__global__ __launch_bounds__(256) void k_scan3(int n) {
    int tid = threadIdx.x, lane = tid & 31, wid = tid >> 5;
    int i0 = blockIdx.x * 1024 + tid * 4;
    int v[4];
#pragma unroll
    for (int k = 0; k < 4; k++) {
        int i = i0 + k;
        v[k] = (i < n) ? g_degcnt[i] : 0;
    }
    int s  = v[0] + v[1] + v[2] + v[3];
    int sc = s;
#pragma unroll
    for (int o = 1; o < 32; o <<= 1) {
        int t = __shfl_up_sync(0xffffffffu, sc, o);
        if (lane >= o) sc += t;
    }
    __shared__ int ws[8];
    if (lane == 31) ws[wid] = sc;
    __syncthreads();
    if (wid == 0) {
        int t = (lane < 8) ? ws[lane] : 0;
#pragma unroll
        for (int o = 1; o < 8; o <<= 1) {
            int u = __shfl_up_sync(0xffffffffu, t, o);
            if (lane >= o) t += u;
        }
        if (lane < 8) ws[lane] = t;
    }
    __syncthreads();
    int base = g_boff[blockIdx.x] + (wid ? ws[wid - 1] : 0) + (sc - s);
#pragma unroll
    for (int k = 0; k < 4; k++) {
        int i = i0 + k;
        if (i < n) {
            g_off[i]    = base;
            g_cur[i]    = base;
            g_invdeg[i] = 1.0f / fmaxf((float)v[k], 1.0f);
            base += v[k];
        }
    }
}

__global__ void k_scatter(const int* __restrict__ src, const int* __restrict__ dst, int e) {
    int i = blockIdx.x * blockDim.x + threadIdx.x;
    if (i < e) {
        int pos    = atomicAdd(&g_cur[dst[i]], 1);
        g_csr[pos] = src[i];
    }
}

// ---------------- aggregation: pre = h + mean_{src->i} h[src]  (warp/node)
__global__ __launch_bounds__(256) void k_agg(const float* __restrict__ x, int n, int first) {
    int node = (blockIdx.x * blockDim.x + threadIdx.x) >> 5;
    int lane = threadIdx.x & 31;
    if (node >= n) return;
    const float* __restrict__ hin = first ? x : (const float*)g_h;
    int beg = g_off[node], end = g_off[node + 1];
    float2 acc = make_float2(0.0f, 0.0f);
    for (int j = beg; j < end; j++) {
        int s    = g_csr[j];
        float2 v = *(const float2*)(hin + s * D + lane * 2);
        acc.x += v.x;
        acc.y += v.y;
    }
    float inv  = g_invdeg[node];
    float2 hv  = *(const float2*)(hin + node * D + lane * 2);
    float2 o;
    o.x = hv.x + acc.x * inv;
    o.y = hv.y + acc.y * inv;
    *(float2*)(g_pre + node * D + lane * 2) = o;
}

// ---------------- GEMM 64x64 tiles, 4x4 per thread --------------------
// MODE 0: z = pre @ W1 + b1          (X = g_pre, Y = g_z)
// MODE 1: h = relu(bn(z)) @ W2 + b2  (X = g_z with BN+ReLU, Y = g_h, pool)
template <int MODE>
__global__ __launch_bounds__(256) void k_gemm(const float* __restrict__ W,
                                              const float* __restrict__ bias,
                                              float* __restrict__ pool, int n, int addflag) {
    __shared__ float sW[64 * 64];
    __shared__ float sX[64 * 68];  // transposed, padded: sX[col*68 + row]
    int tid  = threadIdx.x;
    int brow = blockIdx.x * 64;
    const float* __restrict__ X = (MODE == 0) ? (const float*)g_pre : (const float*)g_z;
    float* __restrict__ Y       = (MODE == 0) ? g_z : g_h;

    // stage W (coalesced)
    {
        const float4* W4 = (const float4*)W;
        float4* sW4      = (float4*)sW;
#pragma unroll
        for (int e = tid; e < 1024; e += 256) sW4[e] = W4[e];
    }
    // stage X transposed
    for (int e = tid; e < 1024; e += 256) {
        int r   = e & 63;   // tile row
        int c4  = e >> 6;   // float4 column group 0..15
        int row = brow + r;
        float4 v = make_float4(0.f, 0.f, 0.f, 0.f);
        if (row < n) v = *(const float4*)(X + row * D + c4 * 4);
        int c = c4 * 4;
        if (MODE == 1) {
            v.x = fmaxf(fmaf(v.x, g_ab[c + 0], g_ab[64 + c + 0]), 0.f);
            v.y = fmaxf(fmaf(v.y, g_ab[c + 1], g_ab[64 + c + 1]), 0.f);
            v.z = fmaxf(fmaf(v.z, g_ab[c + 2], g_ab[64 + c + 2]), 0.f);
            v.w = fmaxf(fmaf(v.w, g_ab[c + 3], g_ab[64 + c + 3]), 0.f);
        }
        sX[(c + 0) * 68 + r] = v.x;
        sX[(c + 1) * 68 + r] = v.y;
        sX[(c + 2) * 68 + r] = v.z;
        sX[(c + 3) * 68 + r] = v.w;
    }
    __syncthreads();

    int tx = tid & 15, ty = tid >> 4;
    float4 a0 = make_float4(0.f, 0.f, 0.f, 0.f), a1 = a0, a2 = a0, a3 = a0;
#pragma unroll
    for (int k = 0; k < 64; k++) {
        float4 w  = *(const float4*)&sW[k * 64 + tx * 4];
        float4 xv = *(const float4*)&sX[k * 68 + ty * 4];
        a0.x = fmaf(xv.x, w.x, a0.x); a0.y = fmaf(xv.x, w.y, a0.y);
        a0.z = fmaf(xv.x, w.z, a0.z); a0.w = fmaf(xv.x, w.w, a0.w);
        a1.x = fmaf(xv.y, w.x, a1.x); a1.y = fmaf(xv.y, w.y, a1.y);
        a1.z = fmaf(xv.y, w.z, a1.z); a1.w = fmaf(xv.y, w.w, a1.w);
        a2.x = fmaf(xv.z, w.x, a2.x); a2.y = fmaf(xv.z, w.y, a2.y);
        a2.z = fmaf(xv.z, w.z, a2.z); a2.w = fmaf(xv.z, w.w, a2.w);
        a3.x = fmaf(xv.w, w.x, a3.x); a3.y = fmaf(xv.w, w.y, a3.y);
        a3.z = fmaf(xv.w, w.z, a3.z); a3.w = fmaf(xv.w, w.w, a3.w);
    }

    float4 bv = *(const float4*)(bias + tx * 4);
    float4 accs[4] = {a0, a1, a2, a3};
#pragma unroll
    for (int i = 0; i < 4; i++) {
        int r = brow + ty * 4 + i;
        if (r < n) {
            float4 o = accs[i];
            o.x += bv.x; o.y += bv.y; o.z += bv.z; o.w += bv.w;
            *(float4*)(Y + r * D + tx * 4) = o;
            if (MODE == 1) {
                float4* pp = (float4*)(pool + r * D + tx * 4);
                if (addflag) {
                    float4 p = *pp;
                    p.x += o.x; p.y += o.y; p.z += o.z; p.w += o.w;
                    *pp = p;
                } else {
                    *pp = o;
                }
            }
        }
    }
}

// ---------------- BN statistics ----------------
__global__ void k_zstat() {
    if (threadIdx.x < 2 * D) g_stats[threadIdx.x] = 0.0f;
}

__global__ __launch_bounds__(256) void k_stats(int n) {
    int col = threadIdx.x & 63;
    int rg  = threadIdx.x >> 6;  // 0..3
    float s = 0.f, q = 0.f;
    for (int r = blockIdx.x * 4 + rg; r < n; r += gridDim.x * 4) {
        float v = g_z[r * D + col];
        s += v;
        q += v * v;
    }
    __shared__ float ss[4][64];
    __shared__ float qq[4][64];
    ss[rg][col] = s;
    qq[rg][col] = q;
    __syncthreads();
    if (threadIdx.x < 64) {
        int c   = threadIdx.x;
        float S = ss[0][c] + ss[1][c] + ss[2][c] + ss[3][c];
        float Q = qq[0][c] + qq[1][c] + qq[2][c] + qq[3][c];
        atomicAdd(&g_stats[c], S);
        atomicAdd(&g_stats[64 + c], Q);
    }
}

__global__ void k_bnparams(const float* __restrict__ gamma, const float* __restrict__ beta, int n) {
    int c = threadIdx.x;
    if (c < D) {
        float invN = 1.0f / (float)n;
        float mean = g_stats[c] * invN;
        float var  = g_stats[64 + c] * invN - mean * mean;
        float a    = gamma[c] * rsqrtf(var + BN_EPS);
        g_ab[c]      = a;
        g_ab[64 + c] = beta[c] - mean * a;
    }
}

// ---------------- graph pooling: gp = inv_gcnt * segsum(node_pool) -------
__global__ __launch_bounds__(256) void k_gpool(const float* __restrict__ np,
                                               const int* __restrict__ batch,
                                               float* __restrict__ gp, int n) {
    int idx = blockIdx.x * blockDim.x + threadIdx.x;
    if (idx < n * D) {
        int row = idx >> 6;
        int col = idx & 63;
        int b   = batch[row];
        atomicAdd(&gp[b * D + col], np[idx] * g_invg[b]);
    }
}

// ---------------- launch ----------------
extern "C" void kernel_launch(void* const* d_in, const int* in_sizes, int n_in,
                              void* d_out, int out_size) {
    const float* x     = (const float*)d_in[0];
    const int*   ei    = (const int*)d_in[1];
    const int*   batch = (const int*)d_in[2];
    const float* W1    = (const float*)d_in[3];
    const float* b1    = (const float*)d_in[4];
    const float* gamma = (const float*)d_in[5];
    const float* beta  = (const float*)d_in[6];
    const float* W2    = (const float*)d_in[7];
    const float* b2    = (const float*)d_in[8];

    int n = in_sizes[0] / D;
    int e = in_sizes[1] / 2;
    int L = in_sizes[3] / (D * D);
    if (n > NCAP || e > ECAP) return;

    float* np = (float*)d_out;               // node_pool [n, D]
    float* gp = np + (size_t)n * D;          // g_pool    [g, D]
    int g = (out_size - n * D) / D;
    if (g > GCAP) return;

    const int* src = ei;
    const int* dst = ei + e;

    int nb256 = (n + 255) / 256;
    int eb256 = (e + 255) / 256;
    int nscan = (n + 1023) / 1024;

    // graph structure (per call; deterministic)
    k_init<<<nb256, 256>>>(n, g, gp);
    k_deg<<<eb256, 256>>>(dst, e);
    k_gcnt<<<nb256, 256>>>(batch, n);
    k_scan1<<<nscan, 256>>>(n);
    k_scan2<<<1, 128>>>(nscan, n, e, g);
    k_scan3<<<nscan, 256>>>(n);
    k_scatter<<<eb256, 256>>>(src, dst, e);

    int aggBlocks  = (n * 32 + 255) / 256;
    int gemmBlocks = (n + 63) / 64;

    for (int l = 0; l < L; l++) {
        k_agg<<<aggBlocks, 256>>>(x, n, l == 0 ? 1 : 0);
        k_gemm<0><<<gemmBlocks, 256>>>(W1 + l * D * D, b1 + l * D, nullptr, n, 0);
        k_zstat<<<1, 128>>>();
        k_stats<<<512, 256>>>(n);
        k_bnparams<<<1, 64>>>(gamma + l * D, beta + l * D, n);
        k_gemm<1><<<gemmBlocks, 256>>>(W2 + l * D * D, b2 + l * D, np, n, l == 0 ? 0 : 1);
    }

    k_gpool<<<(n * D + 255) / 256, 256>>>(np, batch, gp, n);
}

// round 5
// speedup vs baseline: 1.2240x; 1.0614x over previous
#include <cuda_runtime.h>

#define D 64
#define NCAP 100000
#define ECAP 1600000
#define GCAP 128
#define LCAP 8
#define BN_EPS 1e-5f

// ---------------- device scratch ----------------
__device__ int   g_degcnt[NCAP];
__device__ int   g_off[NCAP + 1];
__device__ int   g_cur[NCAP];
__device__ int   g_csr[ECAP];
__device__ float g_invdeg[NCAP];
__device__ float g_gcnt[GCAP];
__device__ float g_invg[GCAP];
__device__ float g_h[NCAP * D];
__device__ float g_z[NCAP * D];
__device__ float g_statsall[LCAP * 2 * D];
__device__ float g_ab[2 * D];
__device__ int   g_bsum[128];
__device__ int   g_boff[128];

// ---------------- init: zero counters + stats + g_pool ----------------
__global__ void k_init(int n, int g, int L, float* __restrict__ gp) {
    int i = blockIdx.x * blockDim.x + threadIdx.x;
    if (i < n) g_degcnt[i] = 0;
    if (i < g) g_gcnt[i] = 0.0f;
    if (i < g * D) gp[i] = 0.0f;
    if (i < L * 2 * D) g_statsall[i] = 0.0f;
}

__global__ void k_deg(const int* __restrict__ dst, int e) {
    int i = blockIdx.x * blockDim.x + threadIdx.x;
    if (i < e) atomicAdd(&g_degcnt[dst[i]], 1);
}

__global__ void k_gcnt(const int* __restrict__ batch, int n) {
    int i = blockIdx.x * blockDim.x + threadIdx.x;
    if (i < n) atomicAdd(&g_gcnt[batch[i]], 1.0f);
}

// ---------------- two-level scan: pass 1, per-block reduce (1024/block) ---
__global__ __launch_bounds__(256) void k_scan1(int n) {
    int tid = threadIdx.x;
    int i0  = blockIdx.x * 1024 + tid * 4;
    int s = 0;
#pragma unroll
    for (int k = 0; k < 4; k++) {
        int i = i0 + k;
        if (i < n) s += g_degcnt[i];
    }
#pragma unroll
    for (int o = 16; o > 0; o >>= 1) s += __shfl_down_sync(0xffffffffu, s, o);
    __shared__ int ws[8];
    if ((tid & 31) == 0) ws[tid >> 5] = s;
    __syncthreads();
    if (tid == 0) {
        int t = 0;
#pragma unroll
        for (int k = 0; k < 8; k++) t += ws[k];
        g_bsum[blockIdx.x] = t;
    }
}

// ---------------- scan pass 2: scan block sums (1 block) + invg + off[n] --
__global__ void k_scan2(int nblk, int n, int e, int g) {
    int tid = threadIdx.x, lane = tid & 31, w = tid >> 5;
    int v  = (tid < nblk) ? g_bsum[tid] : 0;
    int sc = v;
#pragma unroll
    for (int o = 1; o < 32; o <<= 1) {
        int t = __shfl_up_sync(0xffffffffu, sc, o);
        if (lane >= o) sc += t;
    }
    __shared__ int ws[4];
    if (lane == 31) ws[w] = sc;
    __syncthreads();
    int off = 0;
    for (int k = 0; k < w; k++) off += ws[k];
    if (tid < nblk) g_boff[tid] = off + sc - v;
    if (tid == 0) g_off[n] = e;
    if (tid < g) g_invg[tid] = 1.0f / fmaxf(g_gcnt[tid], 1.0f);
}

// ---------------- scan pass 3: local scan + global offset ----------------
__global__ __launch_bounds__(256) void k_scan3(int n) {
    int tid = threadIdx.x, lane = tid & 31, wid = tid >> 5;
    int i0 = blockIdx.x * 1024 + tid * 4;
    int v[4];
#pragma unroll
    for (int k = 0; k < 4; k++) {
        int i = i0 + k;
        v[k] = (i < n) ? g_degcnt[i] : 0;
    }
    int s  = v[0] + v[1] + v[2] + v[3];
    int sc = s;
#pragma unroll
    for (int o = 1; o < 32; o <<= 1) {
        int t = __shfl_up_sync(0xffffffffu, sc, o);
        if (lane >= o) sc += t;
    }
    __shared__ int ws[8];
    if (lane == 31) ws[wid] = sc;
    __syncthreads();
    if (wid == 0) {
        int t = (lane < 8) ? ws[lane] : 0;
#pragma unroll
        for (int o = 1; o < 8; o <<= 1) {
            int u = __shfl_up_sync(0xffffffffu, t, o);
            if (lane >= o) t += u;
        }
        if (lane < 8) ws[lane] = t;
    }
    __syncthreads();
    int base = g_boff[blockIdx.x] + (wid ? ws[wid - 1] : 0) + (sc - s);
#pragma unroll
    for (int k = 0; k < 4; k++) {
        int i = i0 + k;
        if (i < n) {
            g_off[i]    = base;
            g_cur[i]    = base;
            g_invdeg[i] = 1.0f / fmaxf((float)v[k], 1.0f);
            base += v[k];
        }
    }
}

__global__ void k_scatter(const int* __restrict__ src, const int* __restrict__ dst, int e) {
    int i = blockIdx.x * blockDim.x + threadIdx.x;
    if (i < e) {
        int pos    = atomicAdd(&g_cur[dst[i]], 1);
        g_csr[pos] = src[i];
    }
}

// ---------------- GEMM0 fused: agg + GEMM + bias + BN stats --------------
// z = (h + mean_nbr(h)) @ W1 + b1 ; column sum/sumsq -> g_statsall[layer]
// ALL device-symbol pointers resolved in device code (first/layer flags).
__global__ __launch_bounds__(256) void k_gemm0(const float* __restrict__ x,
                                               const float* __restrict__ W,
                                               const float* __restrict__ bias,
                                               int first, int layer, int n) {
    __shared__ float sW[64 * 64];
    __shared__ float sX[64 * 68];
    int tid  = threadIdx.x;
    int brow = blockIdx.x * 64;
    int lane = tid & 31, wrp = tid >> 5;
    const float* __restrict__ hin = first ? x : (const float*)g_h;  // DEVICE-side
    float* __restrict__ stats = g_statsall + layer * 2 * D;         // DEVICE-side

    // stage W
    {
        const float4* W4 = (const float4*)W;
        float4* sW4      = (float4*)sW;
#pragma unroll
        for (int e = tid; e < 1024; e += 256) sW4[e] = W4[e];
    }

    // fused aggregation staging: warp handles 8 rows, lane owns 2 columns
    const float2* h2 = (const float2*)hin;
#pragma unroll 1
    for (int rr = 0; rr < 8; rr++) {
        int r   = wrp * 8 + rr;
        int row = brow + r;
        float2 a = make_float2(0.f, 0.f);
        if (row < n) {
            int beg = g_off[row], end = g_off[row + 1];
            for (int jb = beg; jb < end; jb += 32) {
                int cnt = end - jb;
                if (cnt > 32) cnt = 32;
                int sv = (lane < cnt) ? g_csr[jb + lane] : 0;
                for (int k = 0; k < cnt; k++) {
                    int s    = __shfl_sync(0xffffffffu, sv, k);
                    float2 v = h2[s * 32 + lane];
                    a.x += v.x;
                    a.y += v.y;
                }
            }
            float inv = g_invdeg[row];
            float2 hv = h2[row * 32 + lane];
            a.x = hv.x + a.x * inv;
            a.y = hv.y + a.y * inv;
        }
        sX[(2 * lane) * 68 + r]     = a.x;
        sX[(2 * lane + 1) * 68 + r] = a.y;
    }
    __syncthreads();

    int tx = tid & 15, ty = tid >> 4;
    float4 a0 = make_float4(0.f, 0.f, 0.f, 0.f), a1 = a0, a2 = a0, a3 = a0;
#pragma unroll
    for (int k = 0; k < 64; k++) {
        float4 w  = *(const float4*)&sW[k * 64 + tx * 4];
        float4 xv = *(const float4*)&sX[k * 68 + ty * 4];
        a0.x = fmaf(xv.x, w.x, a0.x); a0.y = fmaf(xv.x, w.y, a0.y);
        a0.z = fmaf(xv.x, w.z, a0.z); a0.w = fmaf(xv.x, w.w, a0.w);
        a1.x = fmaf(xv.y, w.x, a1.x); a1.y = fmaf(xv.y, w.y, a1.y);
        a1.z = fmaf(xv.y, w.z, a1.z); a1.w = fmaf(xv.y, w.w, a1.w);
        a2.x = fmaf(xv.z, w.x, a2.x); a2.y = fmaf(xv.z, w.y, a2.y);
        a2.z = fmaf(xv.z, w.z, a2.z); a2.w = fmaf(xv.z, w.w, a2.w);
        a3.x = fmaf(xv.w, w.x, a3.x); a3.y = fmaf(xv.w, w.y, a3.y);
        a3.z = fmaf(xv.w, w.z, a3.z); a3.w = fmaf(xv.w, w.w, a3.w);
    }

    float4 bv = *(const float4*)(bias + tx * 4);
    float4 accs[4] = {a0, a1, a2, a3};
    float4 s = make_float4(0.f, 0.f, 0.f, 0.f);
    float4 q = make_float4(0.f, 0.f, 0.f, 0.f);
#pragma unroll
    for (int i = 0; i < 4; i++) {
        int r = brow + ty * 4 + i;
        if (r < n) {
            float4 o = accs[i];
            o.x += bv.x; o.y += bv.y; o.z += bv.z; o.w += bv.w;
            *(float4*)(g_z + r * D + tx * 4) = o;
            s.x += o.x; s.y += o.y; s.z += o.z; s.w += o.w;
            q.x = fmaf(o.x, o.x, q.x); q.y = fmaf(o.y, o.y, q.y);
            q.z = fmaf(o.z, o.z, q.z); q.w = fmaf(o.w, o.w, q.w);
        }
    }
    __syncthreads();
    *(float4*)&sW[ty * 64 + tx * 4] = s;   // reuse smem: [16][64] partial sums
    *(float4*)&sX[ty * 64 + tx * 4] = q;
    __syncthreads();
    if (tid < 64) {
        float S = 0.f, Q = 0.f;
#pragma unroll
        for (int k = 0; k < 16; k++) {
            S += sW[k * 64 + tid];
            Q += sX[k * 64 + tid];
        }
        atomicAdd(&stats[tid], S);
        atomicAdd(&stats[64 + tid], Q);
    }
}

// ---------------- BN params ----------------
__global__ void k_bnparams(const float* __restrict__ gamma, const float* __restrict__ beta,
                           int layer, int n) {
    int c = threadIdx.x;
    const float* __restrict__ stats = g_statsall + layer * 2 * D;  // device-side
    if (c < D) {
        float invN = 1.0f / (float)n;
        float mean = stats[c] * invN;
        float var  = stats[64 + c] * invN - mean * mean;
        float a    = gamma[c] * rsqrtf(var + BN_EPS);
        g_ab[c]      = a;
        g_ab[64 + c] = beta[c] - mean * a;
    }
}

// ---------------- GEMM1: h = relu(bn(z)) @ W2 + b2, pool epilogue --------
__global__ __launch_bounds__(256) void k_gemm1(const float* __restrict__ W,
                                               const float* __restrict__ bias,
                                               float* __restrict__ pool, int n, int addflag) {
    __shared__ float sW[64 * 64];
    __shared__ float sX[64 * 68];
    int tid  = threadIdx.x;
    int brow = blockIdx.x * 64;

    {
        const float4* W4 = (const float4*)W;
        float4* sW4      = (float4*)sW;
#pragma unroll
        for (int e = tid; e < 1024; e += 256) sW4[e] = W4[e];
    }
    for (int e = tid; e < 1024; e += 256) {
        int r   = e & 63;
        int c4  = e >> 6;
        int row = brow + r;
        float4 v = make_float4(0.f, 0.f, 0.f, 0.f);
        if (row < n) v = *(const float4*)(g_z + row * D + c4 * 4);
        int c = c4 * 4;
        v.x = fmaxf(fmaf(v.x, g_ab[c + 0], g_ab[64 + c + 0]), 0.f);
        v.y = fmaxf(fmaf(v.y, g_ab[c + 1], g_ab[64 + c + 1]), 0.f);
        v.z = fmaxf(fmaf(v.z, g_ab[c + 2], g_ab[64 + c + 2]), 0.f);
        v.w = fmaxf(fmaf(v.w, g_ab[c + 3], g_ab[64 + c + 3]), 0.f);
        sX[(c + 0) * 68 + r] = v.x;
        sX[(c + 1) * 68 + r] = v.y;
        sX[(c + 2) * 68 + r] = v.z;
        sX[(c + 3) * 68 + r] = v.w;
    }
    __syncthreads();

    int tx = tid & 15, ty = tid >> 4;
    float4 a0 = make_float4(0.f, 0.f, 0.f, 0.f), a1 = a0, a2 = a0, a3 = a0;
#pragma unroll
    for (int k = 0; k < 64; k++) {
        float4 w  = *(const float4*)&sW[k * 64 + tx * 4];
        float4 xv = *(const float4*)&sX[k * 68 + ty * 4];
        a0.x = fmaf(xv.x, w.x, a0.x); a0.y = fmaf(xv.x, w.y, a0.y);
        a0.z = fmaf(xv.x, w.z, a0.z); a0.w = fmaf(xv.x, w.w, a0.w);
        a1.x = fmaf(xv.y, w.x, a1.x); a1.y = fmaf(xv.y, w.y, a1.y);
        a1.z = fmaf(xv.y, w.z, a1.z); a1.w = fmaf(xv.y, w.w, a1.w);
        a2.x = fmaf(xv.z, w.x, a2.x); a2.y = fmaf(xv.z, w.y, a2.y);
        a2.z = fmaf(xv.z, w.z, a2.z); a2.w = fmaf(xv.z, w.w, a2.w);
        a3.x = fmaf(xv.w, w.x, a3.x); a3.y = fmaf(xv.w, w.y, a3.y);
        a3.z = fmaf(xv.w, w.z, a3.z); a3.w = fmaf(xv.w, w.w, a3.w);
    }

    float4 bv = *(const float4*)(bias + tx * 4);
    float4 accs[4] = {a0, a1, a2, a3};
#pragma unroll
    for (int i = 0; i < 4; i++) {
        int r = brow + ty * 4 + i;
        if (r < n) {
            float4 o = accs[i];
            o.x += bv.x; o.y += bv.y; o.z += bv.z; o.w += bv.w;
            *(float4*)(g_h + r * D + tx * 4) = o;
            float4* pp = (float4*)(pool + r * D + tx * 4);
            if (addflag) {
                float4 p = *pp;
                p.x += o.x; p.y += o.y; p.z += o.z; p.w += o.w;
                *pp = p;
            } else {
                *pp = o;
            }
        }
    }
}

// ---------------- graph pooling (run-aware, batch sorted) -----------------
__global__ __launch_bounds__(256) void k_gpool(const float* __restrict__ np,
                                               const int* __restrict__ batch,
                                               float* __restrict__ gp, int n) {
    int col = threadIdx.x & 63;
    int rg  = threadIdx.x >> 6;  // 0..3
    int start = blockIdx.x * 1024;
    int end   = start + 1024;
    if (end > n) end = n;
    float acc = 0.f;
    int curb  = -1;
    for (int r = start + rg; r < end; r += 4) {
        int b = batch[r];
        if (b != curb) {
            if (curb >= 0) atomicAdd(&gp[curb * D + col], acc * g_invg[curb]);
            curb = b;
            acc  = 0.f;
        }
        acc += np[r * D + col];
    }
    if (curb >= 0) atomicAdd(&gp[curb * D + col], acc * g_invg[curb]);
}

// ---------------- launch (NO device-symbol references in host code!) ------
extern "C" void kernel_launch(void* const* d_in, const int* in_sizes, int n_in,
                              void* d_out, int out_size) {
    const float* x     = (const float*)d_in[0];
    const int*   ei    = (const int*)d_in[1];
    const int*   batch = (const int*)d_in[2];
    const float* W1    = (const float*)d_in[3];
    const float* b1    = (const float*)d_in[4];
    const float* gamma = (const float*)d_in[5];
    const float* beta  = (const float*)d_in[6];
    const float* W2    = (const float*)d_in[7];
    const float* b2    = (const float*)d_in[8];

    int n = in_sizes[0] / D;
    int e = in_sizes[1] / 2;
    int L = in_sizes[3] / (D * D);
    if (n > NCAP || e > ECAP || L > LCAP) return;

    float* np = (float*)d_out;
    float* gp = np + (size_t)n * D;
    int g = (out_size - n * D) / D;
    if (g > GCAP) return;

    const int* src = ei;
    const int* dst = ei + e;

    int nb256 = (n + 255) / 256;
    int eb256 = (e + 255) / 256;
    int nscan = (n + 1023) / 1024;

    int initN = n;
    if (g * D > initN) initN = g * D;
    if (L * 2 * D > initN) initN = L * 2 * D;

    k_init<<<(initN + 255) / 256, 256>>>(n, g, L, gp);
    k_deg<<<eb256, 256>>>(dst, e);
    k_gcnt<<<nb256, 256>>>(batch, n);
    k_scan1<<<nscan, 256>>>(n);
    k_scan2<<<1, 128>>>(nscan, n, e, g);
    k_scan3<<<nscan, 256>>>(n);
    k_scatter<<<eb256, 256>>>(src, dst, e);

    int gemmBlocks = (n + 63) / 64;
    for (int l = 0; l < L; l++) {
        k_gemm0<<<gemmBlocks, 256>>>(x, W1 + l * D * D, b1 + l * D, l == 0 ? 1 : 0, l, n);
        k_bnparams<<<1, 64>>>(gamma + l * D, beta + l * D, l, n);
        k_gemm1<<<gemmBlocks, 256>>>(W2 + l * D * D, b2 + l * D, np, n, l == 0 ? 0 : 1);
    }

    k_gpool<<<nscan, 256>>>(np, batch, gp, n);
}